// round 2
// baseline (speedup 1.0000x reference)
#include <cuda_runtime.h>

#define N_NODES 50000
#define N_EDGES 640000
#define HD      128
#define T_TGT   100

// ---------------- scratch (static device globals; no runtime allocation) ----
__device__ float g_deg [N_NODES];          // deg, then dinv (in place)
__device__ float g_norm[N_EDGES];          // per-edge coefficient
__device__ float g_xw  [N_NODES * HD];     // X @ W of current layer
__device__ float g_bufA[N_NODES * HD];     // ping
__device__ float g_bufB[N_NODES * HD];     // pong

// ---------------- degree / coefficient precompute ---------------------------
__global__ void k_init_deg() {
    int i = blockIdx.x * blockDim.x + threadIdx.x;
    if (i < N_NODES) g_deg[i] = 1.0f;           // self-loop contributes +1
}

__global__ void k_accum_deg(const int* __restrict__ dst, const float* __restrict__ ew) {
    int e = blockIdx.x * blockDim.x + threadIdx.x;
    if (e < N_EDGES) atomicAdd(&g_deg[dst[e]], ew[e]);
}

__global__ void k_dinv() {
    int i = blockIdx.x * blockDim.x + threadIdx.x;
    if (i < N_NODES) {
        float d = g_deg[i];
        g_deg[i] = rsqrtf(fmaxf(d, 1e-12f));    // now holds dinv
    }
}

__global__ void k_coeff(const int* __restrict__ src, const int* __restrict__ dst,
                        const float* __restrict__ ew) {
    int e = blockIdx.x * blockDim.x + threadIdx.x;
    if (e < N_EDGES) g_norm[e] = g_deg[src[e]] * ew[e] * g_deg[dst[e]];
}

// ---------------- SGEMM: C[M,128] = A[M,128] @ W[128,128] -------------------
// 128x128 block tile, BK=16, 256 threads, 8x8 per-thread tile.
__global__ __launch_bounds__(256) void k_gemm(const float* __restrict__ A,
                                              const float* __restrict__ W,
                                              float* __restrict__ C, int M) {
    __shared__ float As[16][128];   // transposed: As[k][m]
    __shared__ float Bs[16][128];   // Bs[k][n]

    int tid = threadIdx.x;
    int tx = tid & 15, ty = tid >> 4;
    int row0 = blockIdx.x * 128;

    float acc[8][8];
#pragma unroll
    for (int i = 0; i < 8; i++)
#pragma unroll
        for (int j = 0; j < 8; j++) acc[i][j] = 0.0f;

    for (int k0 = 0; k0 < 128; k0 += 16) {
        // load A tile (128 rows x 16 cols) with transpose into As
#pragma unroll
        for (int it = 0; it < 2; it++) {
            int idx = tid + it * 256;            // 0..511 float4s
            int r   = idx >> 2;                  // 0..127 row within tile
            int c4  = (idx & 3) * 4;             // 0,4,8,12
            float4 v = make_float4(0.f, 0.f, 0.f, 0.f);
            int gr = row0 + r;
            if (gr < M) v = *(const float4*)(A + (long)gr * 128 + k0 + c4);
            As[c4 + 0][r] = v.x;
            As[c4 + 1][r] = v.y;
            As[c4 + 2][r] = v.z;
            As[c4 + 3][r] = v.w;
        }
        // load W tile (16 rows x 128 cols)
#pragma unroll
        for (int it = 0; it < 2; it++) {
            int idx = tid + it * 256;            // 0..511 float4s
            int kr  = idx >> 5;                  // 0..15
            int c4  = (idx & 31) * 4;            // 0..124
            *(float4*)&Bs[kr][c4] = *(const float4*)(W + (long)(k0 + kr) * 128 + c4);
        }
        __syncthreads();

#pragma unroll
        for (int kk = 0; kk < 16; kk++) {
            float a[8], b[8];
            *(float4*)&a[0] = *(const float4*)&As[kk][ty * 8];
            *(float4*)&a[4] = *(const float4*)&As[kk][ty * 8 + 4];
            *(float4*)&b[0] = *(const float4*)&Bs[kk][tx * 8];
            *(float4*)&b[4] = *(const float4*)&Bs[kk][tx * 8 + 4];
#pragma unroll
            for (int i = 0; i < 8; i++)
#pragma unroll
                for (int j = 0; j < 8; j++) acc[i][j] += a[i] * b[j];
        }
        __syncthreads();
    }

#pragma unroll
    for (int i = 0; i < 8; i++) {
        int gr = row0 + ty * 8 + i;
        if (gr < M) {
#pragma unroll
            for (int j4 = 0; j4 < 2; j4++) {
                float4 v = make_float4(acc[i][j4 * 4 + 0], acc[i][j4 * 4 + 1],
                                       acc[i][j4 * 4 + 2], acc[i][j4 * 4 + 3]);
                *(float4*)(C + (long)gr * 128 + tx * 8 + j4 * 4) = v;
            }
        }
    }
}

// ---------------- agg init with self-loop term: agg = dinv^2 * xw -----------
__global__ void k_self_init(float* __restrict__ agg, const float* __restrict__ xw) {
    int i = blockIdx.x * blockDim.x + threadIdx.x;   // over N*32 float4s
    if (i < N_NODES * 32) {
        int node = i >> 5;
        float di = g_deg[node];       // dinv
        float s  = di * di;
        float4 v = ((const float4*)xw)[i];
        ((float4*)agg)[i] = make_float4(s * v.x, s * v.y, s * v.z, s * v.w);
    }
}

// ---------------- edge scatter: agg[dst] += norm * xw[src] ------------------
// one warp per edge; lane l handles float4 chunk l (128 floats = 32 float4s)
__global__ __launch_bounds__(256) void k_scatter(const int* __restrict__ src,
                                                 const int* __restrict__ dst,
                                                 const float* __restrict__ xw,
                                                 float* __restrict__ agg) {
    int gw   = (blockIdx.x * blockDim.x + threadIdx.x) >> 5;
    int lane = threadIdx.x & 31;
    if (gw >= N_EDGES) return;
    int   s = src[gw];
    int   d = dst[gw];
    float c = g_norm[gw];
    float4 v = ((const float4*)xw)[(long)s * 32 + lane];
    float* p = agg + (long)d * 128 + lane * 4;
    unsigned long long gp = __cvta_generic_to_global(p);
    asm volatile("red.global.add.v4.f32 [%0], {%1,%2,%3,%4};"
                 :: "l"(gp), "f"(c * v.x), "f"(c * v.y), "f"(c * v.z), "f"(c * v.w)
                 : "memory");
}

// ---------------- finalize: h = relu(agg + b) -------------------------------
__global__ void k_finalize(float* __restrict__ h, const float* __restrict__ b) {
    int i = blockIdx.x * blockDim.x + threadIdx.x;   // over N*32 float4s
    if (i < N_NODES * 32) {
        int c4 = (i & 31) * 4;
        float4 bb = *(const float4*)(b + c4);
        float4 v  = ((float4*)h)[i];
        v.x = fmaxf(v.x + bb.x, 0.f);
        v.y = fmaxf(v.y + bb.y, 0.f);
        v.z = fmaxf(v.z + bb.z, 0.f);
        v.w = fmaxf(v.w + bb.w, 0.f);
        ((float4*)h)[i] = v;
    }
}

// ---------------- head: out = [relu(h3[ace]@Wh+bh)@Wace+bace ;
//                               relu(h3[h2 ]@Wh+bh)@Wh2 +bh2 ] --------------
__global__ __launch_bounds__(128) void k_head(const float* __restrict__ h3,
                                              const int* __restrict__ ace_idx,
                                              const int* __restrict__ h2_idx,
                                              const float* __restrict__ Wh,
                                              const float* __restrict__ bh,
                                              const float* __restrict__ Wace,
                                              const float* __restrict__ bace,
                                              const float* __restrict__ Wh2,
                                              const float* __restrict__ bh2,
                                              float* __restrict__ out) {
    __shared__ float rs[128];
    __shared__ float red[4];
    int bt    = blockIdx.x;            // 0..2T-1
    int which = bt / T_TGT;            // 0 = ace, 1 = h2
    int t     = bt - which * T_TGT;
    int node  = which ? h2_idx[t] : ace_idx[t];
    int j     = threadIdx.x;

    rs[j] = h3[(long)node * 128 + j];
    __syncthreads();

    float acc = 0.f;
#pragma unroll 8
    for (int k = 0; k < 128; k++) acc += rs[k] * Wh[k * 128 + j];

    float hv = fmaxf(acc + bh[j], 0.f);
    float contrib = hv * (which ? Wh2[j] : Wace[j]);
#pragma unroll
    for (int o = 16; o > 0; o >>= 1)
        contrib += __shfl_xor_sync(0xffffffffu, contrib, o);
    if ((j & 31) == 0) red[j >> 5] = contrib;
    __syncthreads();
    if (j == 0)
        out[bt] = red[0] + red[1] + red[2] + red[3] + (which ? bh2[0] : bace[0]);
}

// ---------------- host orchestration ---------------------------------------
extern "C" void kernel_launch(void* const* d_in, const int* in_sizes, int n_in,
                              void* d_out, int out_size) {
    const float* x    = (const float*)d_in[0];
    const int*   ei   = (const int*)  d_in[1];
    const float* ew   = (const float*)d_in[2];
    const int*   ace  = (const int*)  d_in[3];
    const int*   h2i  = (const int*)  d_in[4];
    const float* W1   = (const float*)d_in[5];
    const float* b1   = (const float*)d_in[6];
    const float* W2   = (const float*)d_in[7];
    const float* b2   = (const float*)d_in[8];
    const float* W3   = (const float*)d_in[9];
    const float* b3   = (const float*)d_in[10];
    const float* Wh   = (const float*)d_in[11];
    const float* bh   = (const float*)d_in[12];
    const float* Wace = (const float*)d_in[13];
    const float* bace = (const float*)d_in[14];
    const float* Wh2  = (const float*)d_in[15];
    const float* bh2  = (const float*)d_in[16];
    float* out = (float*)d_out;

    const int* src = ei;
    const int* dst = ei + N_EDGES;

    float *xw, *bufA, *bufB;
    cudaGetSymbolAddress((void**)&xw,   g_xw);
    cudaGetSymbolAddress((void**)&bufA, g_bufA);
    cudaGetSymbolAddress((void**)&bufB, g_bufB);

    const int TPB = 256;
    int gN   = (N_NODES + TPB - 1) / TPB;
    int gE   = (N_EDGES + TPB - 1) / TPB;
    int gNH4 = (N_NODES * 32 + TPB - 1) / TPB;
    int gGEMM = (N_NODES + 127) / 128;
    int gSCAT = (N_EDGES * 32 + TPB - 1) / TPB;

    // degree / edge coefficients
    k_init_deg<<<gN, TPB>>>();
    k_accum_deg<<<gE, TPB>>>(dst, ew);
    k_dinv<<<gN, TPB>>>();
    k_coeff<<<gE, TPB>>>(src, dst, ew);

    // layer 1: x -> bufA
    k_gemm<<<gGEMM, 256>>>(x, W1, xw, N_NODES);
    k_self_init<<<gNH4, TPB>>>(bufA, xw);
    k_scatter<<<gSCAT, TPB>>>(src, dst, xw, bufA);
    k_finalize<<<gNH4, TPB>>>(bufA, b1);

    // layer 2: bufA -> bufB
    k_gemm<<<gGEMM, 256>>>(bufA, W2, xw, N_NODES);
    k_self_init<<<gNH4, TPB>>>(bufB, xw);
    k_scatter<<<gSCAT, TPB>>>(src, dst, xw, bufB);
    k_finalize<<<gNH4, TPB>>>(bufB, b2);

    // layer 3: bufB -> bufA
    k_gemm<<<gGEMM, 256>>>(bufB, W3, xw, N_NODES);
    k_self_init<<<gNH4, TPB>>>(bufA, xw);
    k_scatter<<<gSCAT, TPB>>>(src, dst, xw, bufA);
    k_finalize<<<gNH4, TPB>>>(bufA, b3);

    // head (only the 200 gathered rows)
    k_head<<<2 * T_TGT, 128>>>(bufA, ace, h2i, Wh, bh, Wace, bace, Wh2, bh2, out);
}

// round 3
// speedup vs baseline: 1.0592x; 1.0592x over previous
#include <cuda_runtime.h>

#define N_NODES 50000
#define N_EDGES 640000
#define HD      128
#define T_TGT   100

// ---------------- scratch (static device globals) ---------------------------
__device__ float g_deg [N_NODES];          // deg, then dinv (in place)
__device__ float g_xw  [N_NODES * HD];     // X @ W of current layer
__device__ float g_aggA[N_NODES * HD];     // agg ping
__device__ float g_aggB[N_NODES * HD];     // agg pong

// ---------------- degree precompute -----------------------------------------
__global__ void k_init_deg() {
    int i = blockIdx.x * blockDim.x + threadIdx.x;
    if (i < N_NODES) g_deg[i] = 1.0f;           // self-loop contributes +1
}

__global__ void k_accum_deg(const int* __restrict__ dst, const float* __restrict__ ew) {
    int e = blockIdx.x * blockDim.x + threadIdx.x;
    if (e < N_EDGES) atomicAdd(&g_deg[dst[e]], ew[e]);
}

__global__ void k_dinv() {
    int i = blockIdx.x * blockDim.x + threadIdx.x;
    if (i < N_NODES) {
        float d = g_deg[i];
        g_deg[i] = rsqrtf(fmaxf(d, 1e-12f));    // now holds dinv
    }
}

// ---------------- fused SGEMM ------------------------------------------------
// C[M,128] = act(A)[M,128] @ W[128,128]
//   act(A) = relu(A + Ab) if Ab != nullptr (fused previous-layer bias+relu)
// Epilogue: xw[row]  = C_row
//           agg[row] = dinv[row]^2 * C_row   (self-loop init, fused)
// 128x128 block tile, BK=16, 256 threads, 8x8 per-thread tile.
__global__ __launch_bounds__(256) void k_gemm(const float* __restrict__ A,
                                              const float* __restrict__ Ab,
                                              const float* __restrict__ W,
                                              float* __restrict__ Cxw,
                                              float* __restrict__ Cagg, int M) {
    __shared__ float As[16][128];   // transposed: As[k][m]
    __shared__ float Bs[16][128];   // Bs[k][n]

    int tid = threadIdx.x;
    int tx = tid & 15, ty = tid >> 4;
    int row0 = blockIdx.x * 128;

    float acc[8][8];
#pragma unroll
    for (int i = 0; i < 8; i++)
#pragma unroll
        for (int j = 0; j < 8; j++) acc[i][j] = 0.0f;

    for (int k0 = 0; k0 < 128; k0 += 16) {
        // load A tile (128 rows x 16 cols) with optional bias+relu, transpose
#pragma unroll
        for (int it = 0; it < 2; it++) {
            int idx = tid + it * 256;            // 0..511 float4s
            int r   = idx >> 2;                  // 0..127 row within tile
            int c4  = (idx & 3) * 4;             // 0,4,8,12
            float4 v = make_float4(0.f, 0.f, 0.f, 0.f);
            int gr = row0 + r;
            if (gr < M) v = *(const float4*)(A + (long)gr * 128 + k0 + c4);
            if (Ab) {
                float4 bb = *(const float4*)(Ab + k0 + c4);
                v.x = fmaxf(v.x + bb.x, 0.f);
                v.y = fmaxf(v.y + bb.y, 0.f);
                v.z = fmaxf(v.z + bb.z, 0.f);
                v.w = fmaxf(v.w + bb.w, 0.f);
            }
            As[c4 + 0][r] = v.x;
            As[c4 + 1][r] = v.y;
            As[c4 + 2][r] = v.z;
            As[c4 + 3][r] = v.w;
        }
        // load W tile (16 rows x 128 cols)
#pragma unroll
        for (int it = 0; it < 2; it++) {
            int idx = tid + it * 256;            // 0..511 float4s
            int kr  = idx >> 5;                  // 0..15
            int c4  = (idx & 31) * 4;            // 0..124
            *(float4*)&Bs[kr][c4] = *(const float4*)(W + (long)(k0 + kr) * 128 + c4);
        }
        __syncthreads();

#pragma unroll
        for (int kk = 0; kk < 16; kk++) {
            float a[8], b[8];
            *(float4*)&a[0] = *(const float4*)&As[kk][ty * 8];
            *(float4*)&a[4] = *(const float4*)&As[kk][ty * 8 + 4];
            *(float4*)&b[0] = *(const float4*)&Bs[kk][tx * 8];
            *(float4*)&b[4] = *(const float4*)&Bs[kk][tx * 8 + 4];
#pragma unroll
            for (int i = 0; i < 8; i++)
#pragma unroll
                for (int j = 0; j < 8; j++) acc[i][j] += a[i] * b[j];
        }
        __syncthreads();
    }

#pragma unroll
    for (int i = 0; i < 8; i++) {
        int gr = row0 + ty * 8 + i;
        if (gr < M) {
            float di = g_deg[gr];
            float s  = di * di;
#pragma unroll
            for (int j4 = 0; j4 < 2; j4++) {
                float4 v = make_float4(acc[i][j4 * 4 + 0], acc[i][j4 * 4 + 1],
                                       acc[i][j4 * 4 + 2], acc[i][j4 * 4 + 3]);
                long off = (long)gr * 128 + tx * 8 + j4 * 4;
                *(float4*)(Cxw + off) = v;
                *(float4*)(Cagg + off) = make_float4(s * v.x, s * v.y, s * v.z, s * v.w);
            }
        }
    }
}

// ---------------- edge scatter: agg[dst] += dinv[s]*ew*dinv[d] * xw[src] ----
// one warp per edge; lane l handles float4 chunk l (128 floats = 32 float4s)
__global__ __launch_bounds__(256) void k_scatter(const int* __restrict__ src,
                                                 const int* __restrict__ dst,
                                                 const float* __restrict__ ew,
                                                 const float* __restrict__ xw,
                                                 float* __restrict__ agg) {
    int gw   = (blockIdx.x * blockDim.x + threadIdx.x) >> 5;
    int lane = threadIdx.x & 31;
    if (gw >= N_EDGES) return;
    int   s = src[gw];
    int   d = dst[gw];
    float c = g_deg[s] * ew[gw] * g_deg[d];
    float4 v = ((const float4*)xw)[(long)s * 32 + lane];
    float* p = agg + (long)d * 128 + lane * 4;
    unsigned long long gp = __cvta_generic_to_global(p);
    asm volatile("red.global.add.v4.f32 [%0], {%1,%2,%3,%4};"
                 :: "l"(gp), "f"(c * v.x), "f"(c * v.y), "f"(c * v.z), "f"(c * v.w)
                 : "memory");
}

// ---------------- head ------------------------------------------------------
// h = relu(relu(agg3[node]+b3) @ Wh + bh); out = h @ {Wace|Wh2} + {bace|bh2}
__global__ __launch_bounds__(128) void k_head(const float* __restrict__ agg3,
                                              const float* __restrict__ b3,
                                              const int* __restrict__ ace_idx,
                                              const int* __restrict__ h2_idx,
                                              const float* __restrict__ Wh,
                                              const float* __restrict__ bh,
                                              const float* __restrict__ Wace,
                                              const float* __restrict__ bace,
                                              const float* __restrict__ Wh2,
                                              const float* __restrict__ bh2,
                                              float* __restrict__ out) {
    __shared__ float rs[128];
    __shared__ float red[4];
    int bt    = blockIdx.x;            // 0..2T-1
    int which = bt / T_TGT;            // 0 = ace, 1 = h2
    int t     = bt - which * T_TGT;
    int node  = which ? h2_idx[t] : ace_idx[t];
    int j     = threadIdx.x;

    rs[j] = fmaxf(agg3[(long)node * 128 + j] + b3[j], 0.f);
    __syncthreads();

    float acc = 0.f;
#pragma unroll 8
    for (int k = 0; k < 128; k++) acc += rs[k] * Wh[k * 128 + j];

    float hv = fmaxf(acc + bh[j], 0.f);
    float contrib = hv * (which ? Wh2[j] : Wace[j]);
#pragma unroll
    for (int o = 16; o > 0; o >>= 1)
        contrib += __shfl_xor_sync(0xffffffffu, contrib, o);
    if ((j & 31) == 0) red[j >> 5] = contrib;
    __syncthreads();
    if (j == 0)
        out[bt] = red[0] + red[1] + red[2] + red[3] + (which ? bh2[0] : bace[0]);
}

// ---------------- host orchestration ----------------------------------------
extern "C" void kernel_launch(void* const* d_in, const int* in_sizes, int n_in,
                              void* d_out, int out_size) {
    const float* x    = (const float*)d_in[0];
    const int*   ei   = (const int*)  d_in[1];
    const float* ew   = (const float*)d_in[2];
    const int*   ace  = (const int*)  d_in[3];
    const int*   h2i  = (const int*)  d_in[4];
    const float* W1   = (const float*)d_in[5];
    const float* b1   = (const float*)d_in[6];
    const float* W2   = (const float*)d_in[7];
    const float* b2   = (const float*)d_in[8];
    const float* W3   = (const float*)d_in[9];
    const float* b3   = (const float*)d_in[10];
    const float* Wh   = (const float*)d_in[11];
    const float* bh   = (const float*)d_in[12];
    const float* Wace = (const float*)d_in[13];
    const float* bace = (const float*)d_in[14];
    const float* Wh2  = (const float*)d_in[15];
    const float* bh2  = (const float*)d_in[16];
    float* out = (float*)d_out;

    const int* src = ei;
    const int* dst = ei + N_EDGES;

    float *xw, *aggA, *aggB;
    cudaGetSymbolAddress((void**)&xw,   g_xw);
    cudaGetSymbolAddress((void**)&aggA, g_aggA);
    cudaGetSymbolAddress((void**)&aggB, g_aggB);

    const int TPB = 256;
    int gN    = (N_NODES + TPB - 1) / TPB;
    int gE    = (N_EDGES + TPB - 1) / TPB;
    int gGEMM = (N_NODES + 127) / 128;
    int gSCAT = (N_EDGES * 32 + TPB - 1) / TPB;

    // degree -> dinv
    k_init_deg<<<gN, TPB>>>();
    k_accum_deg<<<gE, TPB>>>(dst, ew);
    k_dinv<<<gN, TPB>>>();

    // layer 1: x -> aggA   (GEMM writes xw + self-loop-initialized agg)
    k_gemm<<<gGEMM, 256>>>(x, nullptr, W1, xw, aggA, N_NODES);
    k_scatter<<<gSCAT, TPB>>>(src, dst, ew, xw, aggA);

    // layer 2: relu(aggA+b1) -> aggB
    k_gemm<<<gGEMM, 256>>>(aggA, b1, W2, xw, aggB, N_NODES);
    k_scatter<<<gSCAT, TPB>>>(src, dst, ew, xw, aggB);

    // layer 3: relu(aggB+b2) -> aggA
    k_gemm<<<gGEMM, 256>>>(aggB, b2, W3, xw, aggA, N_NODES);
    k_scatter<<<gSCAT, TPB>>>(src, dst, ew, xw, aggA);

    // head (applies relu(aggA+b3) on its 200 gathered rows)
    k_head<<<2 * T_TGT, 128>>>(aggA, b3, ace, h2i, Wh, bh, Wace, bace, Wh2, bh2, out);
}

// round 4
// speedup vs baseline: 1.1201x; 1.0575x over previous
#include <cuda_runtime.h>
#include <cstdint>

#define N_NODES 50000
#define N_EDGES 640000
#define HD      128
#define T_TGT   100

// ---------------- scratch (static device globals) ---------------------------
__device__ float g_deg [N_NODES];          // deg, then dinv (in place)
__device__ float g_xw  [N_NODES * HD];     // X @ W of current layer
__device__ float g_aggA[N_NODES * HD];     // agg ping
__device__ float g_aggB[N_NODES * HD];     // agg pong

// ---------------- degree precompute -----------------------------------------
__global__ void k_init_deg() {
    int i = blockIdx.x * blockDim.x + threadIdx.x;
    if (i < N_NODES) g_deg[i] = 1.0f;
}

__global__ void k_accum_deg(const int* __restrict__ dst, const float* __restrict__ ew) {
    int e = blockIdx.x * blockDim.x + threadIdx.x;
    if (e < N_EDGES) atomicAdd(&g_deg[dst[e]], ew[e]);
}

__global__ void k_dinv() {
    int i = blockIdx.x * blockDim.x + threadIdx.x;
    if (i < N_NODES) {
        float d = g_deg[i];
        g_deg[i] = rsqrtf(fmaxf(d, 1e-12f));
    }
}

// ---------------- tf32 helpers ----------------------------------------------
__device__ __forceinline__ void tf32_split(float v, uint32_t& hi, uint32_t& lo) {
    asm("cvt.rna.tf32.f32 %0, %1;" : "=r"(hi) : "f"(v));
    float r = v - __uint_as_float(hi);
    asm("cvt.rna.tf32.f32 %0, %1;" : "=r"(lo) : "f"(r));
}

__device__ __forceinline__ void mma_tf32(float c[4], uint32_t a0, uint32_t a1,
                                         uint32_t a2, uint32_t a3,
                                         uint32_t b0, uint32_t b1) {
    asm volatile(
        "mma.sync.aligned.m16n8k8.row.col.f32.tf32.tf32.f32 "
        "{%0,%1,%2,%3}, {%4,%5,%6,%7}, {%8,%9}, {%0,%1,%2,%3};"
        : "+f"(c[0]), "+f"(c[1]), "+f"(c[2]), "+f"(c[3])
        : "r"(a0), "r"(a1), "r"(a2), "r"(a3), "r"(b0), "r"(b1));
}

// ---------------- fused tf32 GEMM --------------------------------------------
// C[M,128] = act(A)[M,128] @ W[128,128]   (act = relu(A+Ab) if Ab, else A)
// Epilogue: xw = C ; agg = dinv^2 * C  (self-loop init, fused)
// 128x128 block tile, 8 warps (4M x 2N), warp tile 32x64, m16n8k8 3xTF32.
__global__ __launch_bounds__(256, 1) void k_gemm(const float* __restrict__ A,
                                                 const float* __restrict__ Ab,
                                                 const float* __restrict__ W,
                                                 float* __restrict__ Cxw,
                                                 float* __restrict__ Cagg, int M) {
    __shared__ float As[128][36];   // [m][k], KC=32 + pad4 (A-frag LDS conflict-free)
    __shared__ float Bs[32][132];   // [k][n], pad4

    const int tid  = threadIdx.x;
    const int lane = tid & 31;
    const int wid  = tid >> 5;
    const int g    = lane >> 2;      // 0..7
    const int tig  = lane & 3;       // 0..3
    const int wm   = wid >> 1;       // 0..3
    const int wn   = wid & 1;        // 0..1
    const int row0 = blockIdx.x * 128;

    float acc[2][8][4];
#pragma unroll
    for (int mt = 0; mt < 2; mt++)
#pragma unroll
        for (int nt = 0; nt < 8; nt++)
#pragma unroll
            for (int i = 0; i < 4; i++) acc[mt][nt][i] = 0.0f;

    for (int k0 = 0; k0 < 128; k0 += 32) {
        // ---- stage A chunk (128 x 32) with optional bias+relu ----
#pragma unroll
        for (int it = 0; it < 4; it++) {
            int idx = tid + it * 256;        // 0..1023 float4s
            int r   = idx >> 3;              // row in tile
            int c4  = (idx & 7) * 4;         // 0..28
            float4 v = make_float4(0.f, 0.f, 0.f, 0.f);
            int gr = row0 + r;
            if (gr < M) v = *(const float4*)(A + (long)gr * 128 + k0 + c4);
            if (Ab) {
                float4 bb = *(const float4*)(Ab + k0 + c4);
                v.x = fmaxf(v.x + bb.x, 0.f);
                v.y = fmaxf(v.y + bb.y, 0.f);
                v.z = fmaxf(v.z + bb.z, 0.f);
                v.w = fmaxf(v.w + bb.w, 0.f);
            }
            *(float4*)&As[r][c4] = v;
        }
        // ---- stage B chunk (32 x 128) ----
#pragma unroll
        for (int it = 0; it < 4; it++) {
            int idx = tid + it * 256;        // 0..1023 float4s
            int kr  = idx >> 5;              // 0..31
            int c4  = (idx & 31) * 4;        // 0..124
            *(float4*)&Bs[kr][c4] = *(const float4*)(W + (long)(k0 + kr) * 128 + c4);
        }
        __syncthreads();

#pragma unroll
        for (int kk = 0; kk < 32; kk += 8) {
            // A fragments (2 M-tiles), split hi/lo
            uint32_t ah[2][4], al[2][4];
#pragma unroll
            for (int mt = 0; mt < 2; mt++) {
                int mr = wm * 32 + mt * 16;
                float a0 = As[mr + g    ][kk + tig    ];
                float a1 = As[mr + g + 8][kk + tig    ];
                float a2 = As[mr + g    ][kk + tig + 4];
                float a3 = As[mr + g + 8][kk + tig + 4];
                tf32_split(a0, ah[mt][0], al[mt][0]);
                tf32_split(a1, ah[mt][1], al[mt][1]);
                tf32_split(a2, ah[mt][2], al[mt][2]);
                tf32_split(a3, ah[mt][3], al[mt][3]);
            }
            // B fragments (8 N-tiles), split hi/lo
            uint32_t bh[8][2], bl[8][2];
#pragma unroll
            for (int nt = 0; nt < 8; nt++) {
                int nc = wn * 64 + nt * 8 + g;
                float b0 = Bs[kk + tig    ][nc];
                float b1 = Bs[kk + tig + 4][nc];
                tf32_split(b0, bh[nt][0], bl[nt][0]);
                tf32_split(b1, bh[nt][1], bl[nt][1]);
            }
            // 3xTF32 accumulate
#pragma unroll
            for (int mt = 0; mt < 2; mt++)
#pragma unroll
                for (int nt = 0; nt < 8; nt++) {
                    mma_tf32(acc[mt][nt], al[mt][0], al[mt][1], al[mt][2], al[mt][3],
                             bh[nt][0], bh[nt][1]);
                    mma_tf32(acc[mt][nt], ah[mt][0], ah[mt][1], ah[mt][2], ah[mt][3],
                             bl[nt][0], bl[nt][1]);
                    mma_tf32(acc[mt][nt], ah[mt][0], ah[mt][1], ah[mt][2], ah[mt][3],
                             bh[nt][0], bh[nt][1]);
                }
        }
        __syncthreads();
    }

    // ---- epilogue: write xw and agg = dinv^2 * xw ----
#pragma unroll
    for (int mt = 0; mt < 2; mt++) {
        int r0 = row0 + wm * 32 + mt * 16 + g;
        int r1 = r0 + 8;
        float s0 = 0.f, s1 = 0.f;
        if (r0 < M) { float d = g_deg[r0]; s0 = d * d; }
        if (r1 < M) { float d = g_deg[r1]; s1 = d * d; }
#pragma unroll
        for (int nt = 0; nt < 8; nt++) {
            int col = wn * 64 + nt * 8 + 2 * tig;
            if (r0 < M) {
                long off = (long)r0 * 128 + col;
                *(float2*)(Cxw  + off) = make_float2(acc[mt][nt][0], acc[mt][nt][1]);
                *(float2*)(Cagg + off) = make_float2(s0 * acc[mt][nt][0], s0 * acc[mt][nt][1]);
            }
            if (r1 < M) {
                long off = (long)r1 * 128 + col;
                *(float2*)(Cxw  + off) = make_float2(acc[mt][nt][2], acc[mt][nt][3]);
                *(float2*)(Cagg + off) = make_float2(s1 * acc[mt][nt][2], s1 * acc[mt][nt][3]);
            }
        }
    }
}

// ---------------- edge scatter: agg[dst] += dinv[s]*ew*dinv[d] * xw[src] ----
__global__ __launch_bounds__(256) void k_scatter(const int* __restrict__ src,
                                                 const int* __restrict__ dst,
                                                 const float* __restrict__ ew,
                                                 const float* __restrict__ xw,
                                                 float* __restrict__ agg) {
    int gw   = (blockIdx.x * blockDim.x + threadIdx.x) >> 5;
    int lane = threadIdx.x & 31;
    if (gw >= N_EDGES) return;
    int   s = src[gw];
    int   d = dst[gw];
    float c = g_deg[s] * ew[gw] * g_deg[d];
    float4 v = ((const float4*)xw)[(long)s * 32 + lane];
    float* p = agg + (long)d * 128 + lane * 4;
    unsigned long long gp = __cvta_generic_to_global(p);
    asm volatile("red.global.add.v4.f32 [%0], {%1,%2,%3,%4};"
                 :: "l"(gp), "f"(c * v.x), "f"(c * v.y), "f"(c * v.z), "f"(c * v.w)
                 : "memory");
}

// ---------------- head ------------------------------------------------------
__global__ __launch_bounds__(128) void k_head(const float* __restrict__ agg3,
                                              const float* __restrict__ b3,
                                              const int* __restrict__ ace_idx,
                                              const int* __restrict__ h2_idx,
                                              const float* __restrict__ Wh,
                                              const float* __restrict__ bh,
                                              const float* __restrict__ Wace,
                                              const float* __restrict__ bace,
                                              const float* __restrict__ Wh2,
                                              const float* __restrict__ bh2,
                                              float* __restrict__ out) {
    __shared__ float rs[128];
    __shared__ float red[4];
    int bt    = blockIdx.x;
    int which = bt / T_TGT;
    int t     = bt - which * T_TGT;
    int node  = which ? h2_idx[t] : ace_idx[t];
    int j     = threadIdx.x;

    rs[j] = fmaxf(agg3[(long)node * 128 + j] + b3[j], 0.f);
    __syncthreads();

    float acc = 0.f;
#pragma unroll 8
    for (int k = 0; k < 128; k++) acc += rs[k] * Wh[k * 128 + j];

    float hv = fmaxf(acc + bh[j], 0.f);
    float contrib = hv * (which ? Wh2[j] : Wace[j]);
#pragma unroll
    for (int o = 16; o > 0; o >>= 1)
        contrib += __shfl_xor_sync(0xffffffffu, contrib, o);
    if ((j & 31) == 0) red[j >> 5] = contrib;
    __syncthreads();
    if (j == 0)
        out[bt] = red[0] + red[1] + red[2] + red[3] + (which ? bh2[0] : bace[0]);
}

// ---------------- host orchestration ----------------------------------------
extern "C" void kernel_launch(void* const* d_in, const int* in_sizes, int n_in,
                              void* d_out, int out_size) {
    const float* x    = (const float*)d_in[0];
    const int*   ei   = (const int*)  d_in[1];
    const float* ew   = (const float*)d_in[2];
    const int*   ace  = (const int*)  d_in[3];
    const int*   h2i  = (const int*)  d_in[4];
    const float* W1   = (const float*)d_in[5];
    const float* b1   = (const float*)d_in[6];
    const float* W2   = (const float*)d_in[7];
    const float* b2   = (const float*)d_in[8];
    const float* W3   = (const float*)d_in[9];
    const float* b3   = (const float*)d_in[10];
    const float* Wh   = (const float*)d_in[11];
    const float* bh   = (const float*)d_in[12];
    const float* Wace = (const float*)d_in[13];
    const float* bace = (const float*)d_in[14];
    const float* Wh2  = (const float*)d_in[15];
    const float* bh2  = (const float*)d_in[16];
    float* out = (float*)d_out;

    const int* src = ei;
    const int* dst = ei + N_EDGES;

    float *xw, *aggA, *aggB;
    cudaGetSymbolAddress((void**)&xw,   g_xw);
    cudaGetSymbolAddress((void**)&aggA, g_aggA);
    cudaGetSymbolAddress((void**)&aggB, g_aggB);

    const int TPB = 256;
    int gN    = (N_NODES + TPB - 1) / TPB;
    int gE    = (N_EDGES + TPB - 1) / TPB;
    int gGEMM = (N_NODES + 127) / 128;
    int gSCAT = (N_EDGES * 32 + TPB - 1) / TPB;

    k_init_deg<<<gN, TPB>>>();
    k_accum_deg<<<gE, TPB>>>(dst, ew);
    k_dinv<<<gN, TPB>>>();

    // layer 1: x -> aggA
    k_gemm<<<gGEMM, 256>>>(x, nullptr, W1, xw, aggA, N_NODES);
    k_scatter<<<gSCAT, TPB>>>(src, dst, ew, xw, aggA);

    // layer 2: relu(aggA+b1) -> aggB
    k_gemm<<<gGEMM, 256>>>(aggA, b1, W2, xw, aggB, N_NODES);
    k_scatter<<<gSCAT, TPB>>>(src, dst, ew, xw, aggB);

    // layer 3: relu(aggB+b2) -> aggA
    k_gemm<<<gGEMM, 256>>>(aggB, b2, W3, xw, aggA, N_NODES);
    k_scatter<<<gSCAT, TPB>>>(src, dst, ew, xw, aggA);

    // head
    k_head<<<2 * T_TGT, 128>>>(aggA, b3, ace, h2i, Wh, bh, Wace, bace, Wh2, bh2, out);
}

// round 5
// speedup vs baseline: 1.3913x; 1.2422x over previous
#include <cuda_runtime.h>
#include <cuda_bf16.h>
#include <cstdint>

#define N_NODES 50000
#define N_EDGES 640000
#define HD      128
#define T_TGT   100

// ---------------- scratch (static device globals) ---------------------------
__device__ float g_deg   [N_NODES];        // deg, then dinv (in place)
__device__ int   g_cnt   [N_NODES];        // in-degree count
__device__ int   g_rowptr[N_NODES + 1];    // CSR row pointers (by dst)
__device__ int   g_cursor[N_NODES];        // bucket cursors
__device__ int   g_esrc  [N_EDGES];        // CSR: src node per slot
__device__ float g_ecoef [N_EDGES];        // CSR: edge coefficient per slot
__device__ float g_xw    [N_NODES * HD];   // X @ W of current layer
__device__ float g_aggA  [N_NODES * HD];
__device__ float g_aggB  [N_NODES * HD];

// ---------------- degree / CSR build ----------------------------------------
__global__ void k_init() {
    int i = blockIdx.x * blockDim.x + threadIdx.x;
    if (i < N_NODES) { g_deg[i] = 1.0f; g_cnt[i] = 0; }
}

__global__ void k_deg_count(const int* __restrict__ dst, const float* __restrict__ ew) {
    int e = blockIdx.x * blockDim.x + threadIdx.x;
    if (e < N_EDGES) {
        int d = dst[e];
        atomicAdd(&g_deg[d], ew[e]);
        atomicAdd(&g_cnt[d], 1);
    }
}

// single-block exclusive scan of g_cnt -> rowptr/cursor, plus dinv
__global__ __launch_bounds__(1024) void k_scan() {
    __shared__ int part[1024];
    int t = threadIdx.x;
    const int C = (N_NODES + 1023) / 1024;  // 49
    int lo = t * C;
    int hi = lo + C; if (hi > N_NODES) hi = N_NODES;

    int s = 0;
    for (int i = lo; i < hi; i++) s += g_cnt[i];
    part[t] = s;
    __syncthreads();
    for (int off = 1; off < 1024; off <<= 1) {
        int v = (t >= off) ? part[t - off] : 0;
        __syncthreads();
        part[t] += v;
        __syncthreads();
    }
    int run = (t == 0) ? 0 : part[t - 1];
    for (int i = lo; i < hi; i++) {
        g_rowptr[i] = run;
        g_cursor[i] = run;
        run += g_cnt[i];
        float d = g_deg[i];
        g_deg[i] = rsqrtf(fmaxf(d, 1e-12f));   // deg -> dinv
    }
    if (t == 0) g_rowptr[N_NODES] = N_EDGES;
}

__global__ void k_bucket(const int* __restrict__ src, const int* __restrict__ dst,
                         const float* __restrict__ ew) {
    int e = blockIdx.x * blockDim.x + threadIdx.x;
    if (e < N_EDGES) {
        int d = dst[e];
        int s = src[e];
        int pos = atomicAdd(&g_cursor[d], 1);
        g_esrc[pos]  = s;
        g_ecoef[pos] = g_deg[s] * ew[e] * g_deg[d];
    }
}

// ---------------- bf16 split + mma helpers -----------------------------------
__device__ __forceinline__ void split2(float a, float b, uint32_t& hi, uint32_t& lo) {
    __nv_bfloat16 ha = __float2bfloat16_rn(a);
    __nv_bfloat16 hb = __float2bfloat16_rn(b);
    float ra = a - __bfloat162float(ha);
    float rb = b - __bfloat162float(hb);
    __nv_bfloat162 H; H.x = ha; H.y = hb;
    __nv_bfloat162 L; L.x = __float2bfloat16_rn(ra); L.y = __float2bfloat16_rn(rb);
    hi = *(uint32_t*)&H;
    lo = *(uint32_t*)&L;
}

__device__ __forceinline__ void ldm_x4(uint32_t r[4], uint32_t addr) {
    asm volatile("ldmatrix.sync.aligned.m8n8.x4.shared.b16 {%0,%1,%2,%3}, [%4];"
                 : "=r"(r[0]), "=r"(r[1]), "=r"(r[2]), "=r"(r[3]) : "r"(addr));
}
__device__ __forceinline__ void ldm_x2t(uint32_t r[2], uint32_t addr) {
    asm volatile("ldmatrix.sync.aligned.m8n8.x2.trans.shared.b16 {%0,%1}, [%2];"
                 : "=r"(r[0]), "=r"(r[1]) : "r"(addr));
}
__device__ __forceinline__ void mma_bf16(float c[4], const uint32_t a[4], const uint32_t b[2]) {
    asm volatile("mma.sync.aligned.m16n8k16.row.col.f32.bf16.bf16.f32 "
                 "{%0,%1,%2,%3}, {%4,%5,%6,%7}, {%8,%9}, {%0,%1,%2,%3};"
                 : "+f"(c[0]), "+f"(c[1]), "+f"(c[2]), "+f"(c[3])
                 : "r"(a[0]), "r"(a[1]), "r"(a[2]), "r"(a[3]), "r"(b[0]), "r"(b[1]));
}

// ---------------- fused bf16x3 GEMM ------------------------------------------
// C[M,128] = act(A)[M,128] @ W[128,128]  (act = relu(A+Ab) if Ab, else A)
// 128x128 block tile, 8 warps (4M x 2N), warp tile 32x64, m16n8k16 bf16,
// 3-term split: ah*bh + ah*bl + al*bh. K chunked by 32.
__global__ __launch_bounds__(256, 2) void k_gemm(const float* __restrict__ A,
                                                 const float* __restrict__ Ab,
                                                 const float* __restrict__ W,
                                                 float* __restrict__ Cxw, int M) {
    // A tiles: [m][k] bf16, row stride 40 bf16 = 80 B (20 words, conflict-free ldmatrix)
    __shared__ uint32_t As_hi[128][20], As_lo[128][20];
    // B tiles: [k][n] bf16, row stride 136 bf16 = 272 B (68 words, conflict-free)
    __shared__ uint32_t Bs_hi[32][68], Bs_lo[32][68];

    const int tid  = threadIdx.x;
    const int lane = tid & 31;
    const int wid  = tid >> 5;
    const int g    = lane >> 2;      // 0..7
    const int tig  = lane & 3;       // 0..3
    const int wm   = wid >> 1;       // 0..3
    const int wn   = wid & 1;        // 0..1
    const int row0 = blockIdx.x * 128;

    const uint32_t aH = (uint32_t)__cvta_generic_to_shared(&As_hi[0][0]);
    const uint32_t aL = (uint32_t)__cvta_generic_to_shared(&As_lo[0][0]);
    const uint32_t bH = (uint32_t)__cvta_generic_to_shared(&Bs_hi[0][0]);
    const uint32_t bL = (uint32_t)__cvta_generic_to_shared(&Bs_lo[0][0]);

    float acc[2][8][4];
#pragma unroll
    for (int mt = 0; mt < 2; mt++)
#pragma unroll
        for (int nt = 0; nt < 8; nt++)
#pragma unroll
            for (int i = 0; i < 4; i++) acc[mt][nt][i] = 0.0f;

    for (int k0 = 0; k0 < 128; k0 += 32) {
        // ---- stage A chunk (128 x 32) with optional bias+relu, split hi/lo ----
#pragma unroll
        for (int it = 0; it < 4; it++) {
            int idx = tid + it * 256;        // 0..1023 float4s
            int r   = idx >> 3;
            int c4  = (idx & 7) * 4;         // k within chunk: 0..28
            float4 v = make_float4(0.f, 0.f, 0.f, 0.f);
            int gr = row0 + r;
            if (gr < M) v = *(const float4*)(A + (long)gr * 128 + k0 + c4);
            if (Ab) {
                float4 bb = *(const float4*)(Ab + k0 + c4);
                v.x = fmaxf(v.x + bb.x, 0.f);
                v.y = fmaxf(v.y + bb.y, 0.f);
                v.z = fmaxf(v.z + bb.z, 0.f);
                v.w = fmaxf(v.w + bb.w, 0.f);
            }
            uint32_t h0, l0, h1, l1;
            split2(v.x, v.y, h0, l0);
            split2(v.z, v.w, h1, l1);
            int cw = c4 >> 1;
            As_hi[r][cw] = h0; As_hi[r][cw + 1] = h1;
            As_lo[r][cw] = l0; As_lo[r][cw + 1] = l1;
        }
        // ---- stage B chunk (32 x 128), split hi/lo ----
#pragma unroll
        for (int it = 0; it < 4; it++) {
            int idx = tid + it * 256;        // 0..1023 float4s
            int kr  = idx >> 5;              // 0..31
            int c4  = (idx & 31) * 4;        // 0..124
            float4 v = *(const float4*)(W + (long)(k0 + kr) * 128 + c4);
            uint32_t h0, l0, h1, l1;
            split2(v.x, v.y, h0, l0);
            split2(v.z, v.w, h1, l1);
            int cw = c4 >> 1;
            Bs_hi[kr][cw] = h0; Bs_hi[kr][cw + 1] = h1;
            Bs_lo[kr][cw] = l0; Bs_lo[kr][cw + 1] = l1;
        }
        __syncthreads();

#pragma unroll
        for (int kk = 0; kk < 32; kk += 16) {
            uint32_t Ah[2][4], Al[2][4];
#pragma unroll
            for (int mt = 0; mt < 2; mt++) {
                uint32_t off = (uint32_t)(wm * 32 + mt * 16 + (lane & 15)) * 80u
                             + (uint32_t)(kk + ((lane >> 4) << 3)) * 2u;
                ldm_x4(Ah[mt], aH + off);
                ldm_x4(Al[mt], aL + off);
            }
#pragma unroll
            for (int nt = 0; nt < 8; nt++) {
                uint32_t Bh[2], Bl[2];
                uint32_t off = (uint32_t)(kk + (lane & 15)) * 272u
                             + (uint32_t)(wn * 64 + nt * 8) * 2u;
                ldm_x2t(Bh, bH + off);
                ldm_x2t(Bl, bL + off);
#pragma unroll
                for (int mt = 0; mt < 2; mt++) {
                    mma_bf16(acc[mt][nt], Ah[mt], Bh);
                    mma_bf16(acc[mt][nt], Ah[mt], Bl);
                    mma_bf16(acc[mt][nt], Al[mt], Bh);
                }
            }
        }
        __syncthreads();
    }

    // ---- epilogue: write xw ----
#pragma unroll
    for (int mt = 0; mt < 2; mt++) {
        int r0 = row0 + wm * 32 + mt * 16 + g;
        int r1 = r0 + 8;
#pragma unroll
        for (int nt = 0; nt < 8; nt++) {
            int col = wn * 64 + nt * 8 + 2 * tig;
            if (r0 < M)
                *(float2*)(Cxw + (long)r0 * 128 + col) = make_float2(acc[mt][nt][0], acc[mt][nt][1]);
            if (r1 < M)
                *(float2*)(Cxw + (long)r1 * 128 + col) = make_float2(acc[mt][nt][2], acc[mt][nt][3]);
        }
    }
}

// ---------------- CSR gather: agg[d] = dinv^2*xw[d] + sum c_i * xw[src_i] ----
__global__ __launch_bounds__(256) void k_gather(const float* __restrict__ xw,
                                                float* __restrict__ agg) {
    int node = (blockIdx.x * blockDim.x + threadIdx.x) >> 5;
    int lane = threadIdx.x & 31;
    if (node >= N_NODES) return;

    int beg = g_rowptr[node];
    int end = g_rowptr[node + 1];
    float di = g_deg[node];
    float s  = di * di;

    const float4* xw4 = (const float4*)xw;
    float4 v = xw4[(long)node * 32 + lane];
    float4 acc = make_float4(s * v.x, s * v.y, s * v.z, s * v.w);

    int i = beg;
    for (; i + 2 <= end; i += 2) {
        int   s0 = g_esrc[i],     s1 = g_esrc[i + 1];
        float c0 = g_ecoef[i],    c1 = g_ecoef[i + 1];
        float4 v0 = xw4[(long)s0 * 32 + lane];
        float4 v1 = xw4[(long)s1 * 32 + lane];
        acc.x += c0 * v0.x + c1 * v1.x;
        acc.y += c0 * v0.y + c1 * v1.y;
        acc.z += c0 * v0.z + c1 * v1.z;
        acc.w += c0 * v0.w + c1 * v1.w;
    }
    if (i < end) {
        int   s0 = g_esrc[i];
        float c0 = g_ecoef[i];
        float4 v0 = xw4[(long)s0 * 32 + lane];
        acc.x += c0 * v0.x; acc.y += c0 * v0.y;
        acc.z += c0 * v0.z; acc.w += c0 * v0.w;
    }
    ((float4*)agg)[(long)node * 32 + lane] = acc;
}

// ---------------- head ------------------------------------------------------
__global__ __launch_bounds__(128) void k_head(const float* __restrict__ agg3,
                                              const float* __restrict__ b3,
                                              const int* __restrict__ ace_idx,
                                              const int* __restrict__ h2_idx,
                                              const float* __restrict__ Wh,
                                              const float* __restrict__ bh,
                                              const float* __restrict__ Wace,
                                              const float* __restrict__ bace,
                                              const float* __restrict__ Wh2,
                                              const float* __restrict__ bh2,
                                              float* __restrict__ out) {
    __shared__ float rs[128];
    __shared__ float red[4];
    int bt    = blockIdx.x;
    int which = bt / T_TGT;
    int t     = bt - which * T_TGT;
    int node  = which ? h2_idx[t] : ace_idx[t];
    int j     = threadIdx.x;

    rs[j] = fmaxf(agg3[(long)node * 128 + j] + b3[j], 0.f);
    __syncthreads();

    float acc = 0.f;
#pragma unroll 8
    for (int k = 0; k < 128; k++) acc += rs[k] * Wh[k * 128 + j];

    float hv = fmaxf(acc + bh[j], 0.f);
    float contrib = hv * (which ? Wh2[j] : Wace[j]);
#pragma unroll
    for (int o = 16; o > 0; o >>= 1)
        contrib += __shfl_xor_sync(0xffffffffu, contrib, o);
    if ((j & 31) == 0) red[j >> 5] = contrib;
    __syncthreads();
    if (j == 0)
        out[bt] = red[0] + red[1] + red[2] + red[3] + (which ? bh2[0] : bace[0]);
}

// ---------------- host orchestration ----------------------------------------
extern "C" void kernel_launch(void* const* d_in, const int* in_sizes, int n_in,
                              void* d_out, int out_size) {
    const float* x    = (const float*)d_in[0];
    const int*   ei   = (const int*)  d_in[1];
    const float* ew   = (const float*)d_in[2];
    const int*   ace  = (const int*)  d_in[3];
    const int*   h2i  = (const int*)  d_in[4];
    const float* W1   = (const float*)d_in[5];
    const float* b1   = (const float*)d_in[6];
    const float* W2   = (const float*)d_in[7];
    const float* b2   = (const float*)d_in[8];
    const float* W3   = (const float*)d_in[9];
    const float* b3   = (const float*)d_in[10];
    const float* Wh   = (const float*)d_in[11];
    const float* bh   = (const float*)d_in[12];
    const float* Wace = (const float*)d_in[13];
    const float* bace = (const float*)d_in[14];
    const float* Wh2  = (const float*)d_in[15];
    const float* bh2  = (const float*)d_in[16];
    float* out = (float*)d_out;

    const int* src = ei;
    const int* dst = ei + N_EDGES;

    float *xw, *aggA, *aggB;
    cudaGetSymbolAddress((void**)&xw,   g_xw);
    cudaGetSymbolAddress((void**)&aggA, g_aggA);
    cudaGetSymbolAddress((void**)&aggB, g_aggB);

    const int TPB = 256;
    int gN    = (N_NODES + TPB - 1) / TPB;
    int gE    = (N_EDGES + TPB - 1) / TPB;
    int gGEMM = (N_NODES + 127) / 128;
    int gGATH = (N_NODES * 32 + TPB - 1) / TPB;

    // CSR + dinv build
    k_init<<<gN, TPB>>>();
    k_deg_count<<<gE, TPB>>>(dst, ew);
    k_scan<<<1, 1024>>>();
    k_bucket<<<gE, TPB>>>(src, dst, ew);

    // layer 1: x -> aggA
    k_gemm<<<gGEMM, 256>>>(x, nullptr, W1, xw, N_NODES);
    k_gather<<<gGATH, TPB>>>(xw, aggA);

    // layer 2: relu(aggA+b1) -> aggB
    k_gemm<<<gGEMM, 256>>>(aggA, b1, W2, xw, N_NODES);
    k_gather<<<gGATH, TPB>>>(xw, aggB);

    // layer 3: relu(aggB+b2) -> aggA
    k_gemm<<<gGEMM, 256>>>(aggB, b2, W3, xw, N_NODES);
    k_gather<<<gGATH, TPB>>>(xw, aggA);

    // head
    k_head<<<2 * T_TGT, 128>>>(aggA, b3, ace, h2i, Wh, bh, Wace, bace, Wh2, bh2, out);
}

// round 6
// speedup vs baseline: 1.4766x; 1.0613x over previous
#include <cuda_runtime.h>
#include <cuda_bf16.h>
#include <cuda_fp16.h>
#include <cstdint>

#define N_NODES 50000
#define N_EDGES 640000
#define HD      128
#define T_TGT   100

// ---------------- scratch (static device globals) ---------------------------
__device__ float g_deg   [N_NODES];        // deg, then dinv (in place)
__device__ int   g_cnt   [N_NODES];        // in-degree count
__device__ int   g_rowptr[N_NODES + 1];    // CSR row pointers (by dst)
__device__ int   g_cursor[N_NODES];        // bucket cursors
__device__ int2  g_ecsr  [N_EDGES];        // CSR slot: {src, coef bits}
__device__ __align__(16) __half g_xw[N_NODES * HD];   // X @ W (fp16; gather-only)
__device__ float g_aggA  [N_NODES * HD];
__device__ float g_aggB  [N_NODES * HD];

// ---------------- degree / CSR build ----------------------------------------
__global__ void k_init() {
    int i = blockIdx.x * blockDim.x + threadIdx.x;
    if (i < N_NODES) { g_deg[i] = 1.0f; g_cnt[i] = 0; }
}

__global__ void k_deg_count(const int* __restrict__ dst, const float* __restrict__ ew) {
    int e = blockIdx.x * blockDim.x + threadIdx.x;
    if (e < N_EDGES) {
        int d = dst[e];
        atomicAdd(&g_deg[d], ew[e]);
        atomicAdd(&g_cnt[d], 1);
    }
}

// single-block exclusive scan of g_cnt -> rowptr/cursor, plus dinv
__global__ __launch_bounds__(1024) void k_scan() {
    __shared__ int part[1024];
    int t = threadIdx.x;
    const int C = (N_NODES + 1023) / 1024;  // 49
    int lo = t * C;
    int hi = lo + C; if (hi > N_NODES) hi = N_NODES;

    int s = 0;
    for (int i = lo; i < hi; i++) s += g_cnt[i];
    part[t] = s;
    __syncthreads();
    for (int off = 1; off < 1024; off <<= 1) {
        int v = (t >= off) ? part[t - off] : 0;
        __syncthreads();
        part[t] += v;
        __syncthreads();
    }
    int run = (t == 0) ? 0 : part[t - 1];
    for (int i = lo; i < hi; i++) {
        g_rowptr[i] = run;
        g_cursor[i] = run;
        run += g_cnt[i];
        float d = g_deg[i];
        g_deg[i] = rsqrtf(fmaxf(d, 1e-12f));   // deg -> dinv
    }
    if (t == 0) g_rowptr[N_NODES] = N_EDGES;
}

__global__ void k_bucket(const int* __restrict__ src, const int* __restrict__ dst,
                         const float* __restrict__ ew) {
    int e = blockIdx.x * blockDim.x + threadIdx.x;
    if (e < N_EDGES) {
        int d = dst[e];
        int s = src[e];
        float c = g_deg[s] * ew[e] * g_deg[d];
        int pos = atomicAdd(&g_cursor[d], 1);
        g_ecsr[pos] = make_int2(s, __float_as_int(c));
    }
}

// ---------------- bf16 split + mma helpers -----------------------------------
__device__ __forceinline__ void split2(float a, float b, uint32_t& hi, uint32_t& lo) {
    __nv_bfloat16 ha = __float2bfloat16_rn(a);
    __nv_bfloat16 hb = __float2bfloat16_rn(b);
    float ra = a - __bfloat162float(ha);
    float rb = b - __bfloat162float(hb);
    __nv_bfloat162 H; H.x = ha; H.y = hb;
    __nv_bfloat162 L; L.x = __float2bfloat16_rn(ra); L.y = __float2bfloat16_rn(rb);
    hi = *(uint32_t*)&H;
    lo = *(uint32_t*)&L;
}

__device__ __forceinline__ void ldm_x4(uint32_t r[4], uint32_t addr) {
    asm volatile("ldmatrix.sync.aligned.m8n8.x4.shared.b16 {%0,%1,%2,%3}, [%4];"
                 : "=r"(r[0]), "=r"(r[1]), "=r"(r[2]), "=r"(r[3]) : "r"(addr));
}
__device__ __forceinline__ void ldm_x2t(uint32_t r[2], uint32_t addr) {
    asm volatile("ldmatrix.sync.aligned.m8n8.x2.trans.shared.b16 {%0,%1}, [%2];"
                 : "=r"(r[0]), "=r"(r[1]) : "r"(addr));
}
__device__ __forceinline__ void mma_bf16(float c[4], const uint32_t a[4], const uint32_t b[2]) {
    asm volatile("mma.sync.aligned.m16n8k16.row.col.f32.bf16.bf16.f32 "
                 "{%0,%1,%2,%3}, {%4,%5,%6,%7}, {%8,%9}, {%0,%1,%2,%3};"
                 : "+f"(c[0]), "+f"(c[1]), "+f"(c[2]), "+f"(c[3])
                 : "r"(a[0]), "r"(a[1]), "r"(a[2]), "r"(a[3]), "r"(b[0]), "r"(b[1]));
}

// ---------------- fused bf16x3 GEMM ------------------------------------------
// xw(fp16)[M,128] = act(A)[M,128] @ W[128,128]  (act = relu(A+Ab) if Ab)
// 128x128 block tile, 8 warps (4M x 2N), warp tile 32x64, m16n8k16 bf16,
// 3-term split: ah*bh + ah*bl + al*bh. K chunked by 32.
__global__ __launch_bounds__(256, 2) void k_gemm(const float* __restrict__ A,
                                                 const float* __restrict__ Ab,
                                                 const float* __restrict__ W,
                                                 __half* __restrict__ Cxw, int M) {
    __shared__ uint32_t As_hi[128][20], As_lo[128][20];  // row stride 80 B
    __shared__ uint32_t Bs_hi[32][68], Bs_lo[32][68];    // row stride 272 B

    const int tid  = threadIdx.x;
    const int lane = tid & 31;
    const int wid  = tid >> 5;
    const int g    = lane >> 2;
    const int tig  = lane & 3;
    const int wm   = wid >> 1;
    const int wn   = wid & 1;
    const int row0 = blockIdx.x * 128;

    const uint32_t aH = (uint32_t)__cvta_generic_to_shared(&As_hi[0][0]);
    const uint32_t aL = (uint32_t)__cvta_generic_to_shared(&As_lo[0][0]);
    const uint32_t bH = (uint32_t)__cvta_generic_to_shared(&Bs_hi[0][0]);
    const uint32_t bL = (uint32_t)__cvta_generic_to_shared(&Bs_lo[0][0]);

    float acc[2][8][4];
#pragma unroll
    for (int mt = 0; mt < 2; mt++)
#pragma unroll
        for (int nt = 0; nt < 8; nt++)
#pragma unroll
            for (int i = 0; i < 4; i++) acc[mt][nt][i] = 0.0f;

    for (int k0 = 0; k0 < 128; k0 += 32) {
#pragma unroll
        for (int it = 0; it < 4; it++) {
            int idx = tid + it * 256;
            int r   = idx >> 3;
            int c4  = (idx & 7) * 4;
            float4 v = make_float4(0.f, 0.f, 0.f, 0.f);
            int gr = row0 + r;
            if (gr < M) v = *(const float4*)(A + (long)gr * 128 + k0 + c4);
            if (Ab) {
                float4 bb = *(const float4*)(Ab + k0 + c4);
                v.x = fmaxf(v.x + bb.x, 0.f);
                v.y = fmaxf(v.y + bb.y, 0.f);
                v.z = fmaxf(v.z + bb.z, 0.f);
                v.w = fmaxf(v.w + bb.w, 0.f);
            }
            uint32_t h0, l0, h1, l1;
            split2(v.x, v.y, h0, l0);
            split2(v.z, v.w, h1, l1);
            int cw = c4 >> 1;
            As_hi[r][cw] = h0; As_hi[r][cw + 1] = h1;
            As_lo[r][cw] = l0; As_lo[r][cw + 1] = l1;
        }
#pragma unroll
        for (int it = 0; it < 4; it++) {
            int idx = tid + it * 256;
            int kr  = idx >> 5;
            int c4  = (idx & 31) * 4;
            float4 v = *(const float4*)(W + (long)(k0 + kr) * 128 + c4);
            uint32_t h0, l0, h1, l1;
            split2(v.x, v.y, h0, l0);
            split2(v.z, v.w, h1, l1);
            int cw = c4 >> 1;
            Bs_hi[kr][cw] = h0; Bs_hi[kr][cw + 1] = h1;
            Bs_lo[kr][cw] = l0; Bs_lo[kr][cw + 1] = l1;
        }
        __syncthreads();

#pragma unroll
        for (int kk = 0; kk < 32; kk += 16) {
            uint32_t Ah[2][4], Al[2][4];
#pragma unroll
            for (int mt = 0; mt < 2; mt++) {
                uint32_t off = (uint32_t)(wm * 32 + mt * 16 + (lane & 15)) * 80u
                             + (uint32_t)(kk + ((lane >> 4) << 3)) * 2u;
                ldm_x4(Ah[mt], aH + off);
                ldm_x4(Al[mt], aL + off);
            }
#pragma unroll
            for (int nt = 0; nt < 8; nt++) {
                uint32_t Bh[2], Bl[2];
                uint32_t off = (uint32_t)(kk + (lane & 15)) * 272u
                             + (uint32_t)(wn * 64 + nt * 8) * 2u;
                ldm_x2t(Bh, bH + off);
                ldm_x2t(Bl, bL + off);
#pragma unroll
                for (int mt = 0; mt < 2; mt++) {
                    mma_bf16(acc[mt][nt], Ah[mt], Bh);
                    mma_bf16(acc[mt][nt], Ah[mt], Bl);
                    mma_bf16(acc[mt][nt], Al[mt], Bh);
                }
            }
        }
        __syncthreads();
    }

    // ---- epilogue: write xw as fp16 (half2 per register pair) ----
    __half2* xh2 = (__half2*)Cxw;
#pragma unroll
    for (int mt = 0; mt < 2; mt++) {
        int r0 = row0 + wm * 32 + mt * 16 + g;
        int r1 = r0 + 8;
#pragma unroll
        for (int nt = 0; nt < 8; nt++) {
            int colh = (wn * 64 + nt * 8 + 2 * tig) >> 1;   // half2 index in row
            if (r0 < M)
                xh2[(long)r0 * 64 + colh] = __floats2half2_rn(acc[mt][nt][0], acc[mt][nt][1]);
            if (r1 < M)
                xh2[(long)r1 * 64 + colh] = __floats2half2_rn(acc[mt][nt][2], acc[mt][nt][3]);
        }
    }
}

// ---------------- CSR gather: agg[d] = dinv^2*xw[d] + sum c_i * xw[src_i] ----
// one warp per dst node; lane covers 4 columns (uint2 = 4 halves)
__global__ __launch_bounds__(256) void k_gather(const __half* __restrict__ xw,
                                                float* __restrict__ agg) {
    int node = (blockIdx.x * blockDim.x + threadIdx.x) >> 5;
    int lane = threadIdx.x & 31;
    if (node >= N_NODES) return;

    int beg = g_rowptr[node];
    int end = g_rowptr[node + 1];
    float di = g_deg[node];
    float s  = di * di;

    const uint2* xv = (const uint2*)xw;   // 32 uint2 per row

    float4 acc;
    {
        uint2 u = __ldg(&xv[(long)node * 32 + lane]);
        float2 a = __half22float2(*(__half2*)&u.x);
        float2 b = __half22float2(*(__half2*)&u.y);
        acc = make_float4(s * a.x, s * a.y, s * b.x, s * b.y);
    }

    int i = beg;
    for (; i + 4 <= end; i += 4) {
        int2 p0 = __ldg(&g_ecsr[i]);
        int2 p1 = __ldg(&g_ecsr[i + 1]);
        int2 p2 = __ldg(&g_ecsr[i + 2]);
        int2 p3 = __ldg(&g_ecsr[i + 3]);
        uint2 u0 = __ldg(&xv[(long)p0.x * 32 + lane]);
        uint2 u1 = __ldg(&xv[(long)p1.x * 32 + lane]);
        uint2 u2 = __ldg(&xv[(long)p2.x * 32 + lane]);
        uint2 u3 = __ldg(&xv[(long)p3.x * 32 + lane]);
        float c0 = __int_as_float(p0.y), c1 = __int_as_float(p1.y);
        float c2 = __int_as_float(p2.y), c3 = __int_as_float(p3.y);
        {
            float2 a = __half22float2(*(__half2*)&u0.x);
            float2 b = __half22float2(*(__half2*)&u0.y);
            acc.x += c0 * a.x; acc.y += c0 * a.y; acc.z += c0 * b.x; acc.w += c0 * b.y;
        }
        {
            float2 a = __half22float2(*(__half2*)&u1.x);
            float2 b = __half22float2(*(__half2*)&u1.y);
            acc.x += c1 * a.x; acc.y += c1 * a.y; acc.z += c1 * b.x; acc.w += c1 * b.y;
        }
        {
            float2 a = __half22float2(*(__half2*)&u2.x);
            float2 b = __half22float2(*(__half2*)&u2.y);
            acc.x += c2 * a.x; acc.y += c2 * a.y; acc.z += c2 * b.x; acc.w += c2 * b.y;
        }
        {
            float2 a = __half22float2(*(__half2*)&u3.x);
            float2 b = __half22float2(*(__half2*)&u3.y);
            acc.x += c3 * a.x; acc.y += c3 * a.y; acc.z += c3 * b.x; acc.w += c3 * b.y;
        }
    }
    for (; i < end; i++) {
        int2 p = __ldg(&g_ecsr[i]);
        float c = __int_as_float(p.y);
        uint2 u = __ldg(&xv[(long)p.x * 32 + lane]);
        float2 a = __half22float2(*(__half2*)&u.x);
        float2 b = __half22float2(*(__half2*)&u.y);
        acc.x += c * a.x; acc.y += c * a.y; acc.z += c * b.x; acc.w += c * b.y;
    }
    ((float4*)agg)[(long)node * 32 + lane] = acc;
}

// ---------------- head ------------------------------------------------------
__global__ __launch_bounds__(128) void k_head(const float* __restrict__ agg3,
                                              const float* __restrict__ b3,
                                              const int* __restrict__ ace_idx,
                                              const int* __restrict__ h2_idx,
                                              const float* __restrict__ Wh,
                                              const float* __restrict__ bh,
                                              const float* __restrict__ Wace,
                                              const float* __restrict__ bace,
                                              const float* __restrict__ Wh2,
                                              const float* __restrict__ bh2,
                                              float* __restrict__ out) {
    __shared__ float rs[128];
    __shared__ float red[4];
    int bt    = blockIdx.x;
    int which = bt / T_TGT;
    int t     = bt - which * T_TGT;
    int node  = which ? h2_idx[t] : ace_idx[t];
    int j     = threadIdx.x;

    rs[j] = fmaxf(agg3[(long)node * 128 + j] + b3[j], 0.f);
    __syncthreads();

    float acc = 0.f;
#pragma unroll 8
    for (int k = 0; k < 128; k++) acc += rs[k] * Wh[k * 128 + j];

    float hv = fmaxf(acc + bh[j], 0.f);
    float contrib = hv * (which ? Wh2[j] : Wace[j]);
#pragma unroll
    for (int o = 16; o > 0; o >>= 1)
        contrib += __shfl_xor_sync(0xffffffffu, contrib, o);
    if ((j & 31) == 0) red[j >> 5] = contrib;
    __syncthreads();
    if (j == 0)
        out[bt] = red[0] + red[1] + red[2] + red[3] + (which ? bh2[0] : bace[0]);
}

// ---------------- host orchestration ----------------------------------------
extern "C" void kernel_launch(void* const* d_in, const int* in_sizes, int n_in,
                              void* d_out, int out_size) {
    const float* x    = (const float*)d_in[0];
    const int*   ei   = (const int*)  d_in[1];
    const float* ew   = (const float*)d_in[2];
    const int*   ace  = (const int*)  d_in[3];
    const int*   h2i  = (const int*)  d_in[4];
    const float* W1   = (const float*)d_in[5];
    const float* b1   = (const float*)d_in[6];
    const float* W2   = (const float*)d_in[7];
    const float* b2   = (const float*)d_in[8];
    const float* W3   = (const float*)d_in[9];
    const float* b3   = (const float*)d_in[10];
    const float* Wh   = (const float*)d_in[11];
    const float* bh   = (const float*)d_in[12];
    const float* Wace = (const float*)d_in[13];
    const float* bace = (const float*)d_in[14];
    const float* Wh2  = (const float*)d_in[15];
    const float* bh2  = (const float*)d_in[16];
    float* out = (float*)d_out;

    const int* src = ei;
    const int* dst = ei + N_EDGES;

    __half* xw;
    float *aggA, *aggB;
    cudaGetSymbolAddress((void**)&xw,   g_xw);
    cudaGetSymbolAddress((void**)&aggA, g_aggA);
    cudaGetSymbolAddress((void**)&aggB, g_aggB);

    const int TPB = 256;
    int gN    = (N_NODES + TPB - 1) / TPB;
    int gE    = (N_EDGES + TPB - 1) / TPB;
    int gGEMM = (N_NODES + 127) / 128;
    int gGATH = (N_NODES * 32 + TPB - 1) / TPB;

    // CSR + dinv build
    k_init<<<gN, TPB>>>();
    k_deg_count<<<gE, TPB>>>(dst, ew);
    k_scan<<<1, 1024>>>();
    k_bucket<<<gE, TPB>>>(src, dst, ew);

    // layer 1: x -> aggA
    k_gemm<<<gGEMM, 256>>>(x, nullptr, W1, xw, N_NODES);
    k_gather<<<gGATH, TPB>>>(xw, aggA);

    // layer 2: relu(aggA+b1) -> aggB
    k_gemm<<<gGEMM, 256>>>(aggA, b1, W2, xw, N_NODES);
    k_gather<<<gGATH, TPB>>>(xw, aggB);

    // layer 3: relu(aggB+b2) -> aggA
    k_gemm<<<gGEMM, 256>>>(aggB, b2, W3, xw, N_NODES);
    k_gather<<<gGATH, TPB>>>(xw, aggA);

    // head
    k_head<<<2 * T_TGT, 128>>>(aggA, b3, ace, h2i, Wh, bh, Wace, bace, Wh2, bh2, out);
}